// round 10
// baseline (speedup 1.0000x reference)
#include <cuda_runtime.h>
#include <cstdint>

#define Bdim 256
#define Udim 512
#define Ddim 512
#define N4U  2048

typedef unsigned long long ull;

// ---------------- scratch ----------------
__device__ float g_pre [Bdim * N4U];           // gates pre-activations [B, 4U]
__device__ float g_hw  [Bdim * Udim];          // h_tm1 @ w
__device__ float g_part[Bdim * 128 * Udim];    // 128 partials per (b,v)  (67MB)
__device__ float g_g   [Bdim * Udim];          // eta[b,v]*itc[b,v]

// ---------------- packed f32x2 helpers ----------------
__device__ __forceinline__ ull pk2(float x, float y) {
    ull r; asm("mov.b64 %0, {%1, %2};" : "=l"(r) : "f"(x), "f"(y)); return r;
}
__device__ __forceinline__ ull fma2(ull a, ull b, ull c) {
    ull d; asm("fma.rn.f32x2 %0, %1, %2, %3;" : "=l"(d) : "l"(a), "l"(b), "l"(c)); return d;
}
__device__ __forceinline__ float2 upk(ull v) {
    float2 r; asm("mov.b64 {%0, %1}, %2;" : "=f"(r.x), "=f"(r.y) : "l"(v)); return r;
}

// =======================================================================
// Phase 1: one kernel
//   [0, 256)        : gates GEMM, 32x64 tiles
//   [256, 320)      : hw GEMM,    32x64 tiles
//   [320, 320+16384): hebb partial reduce — NO smem, NO syncthreads,
//                     pure per-thread fold (exact update-kernel shape)
// =======================================================================

__device__ __forceinline__ void gemm32x64(
    const float* __restrict__ A1, const float* __restrict__ B1,
    const float* __restrict__ A2, const float* __restrict__ B2,
    const float* __restrict__ bias, float* __restrict__ C,
    int N, int m0, int n0, bool do_rec, bool add_bias, float* smem)
{
    const int K = 512;
    float (*As)[32] = (float(*)[32])smem;
    float (*Bs)[64] = (float(*)[64])(smem + 512);

    int tid = threadIdx.x;
    int tx  = tid & 15;
    int ty  = tid >> 4;

    ull acc[2][2];
    acc[0][0] = acc[0][1] = acc[1][0] = acc[1][1] = 0ull;

    int npass = do_rec ? 2 : 1;
    for (int pass = 0; pass < npass; ++pass) {
        const float* A = pass ? A2 : A1;
        const float* B = pass ? B2 : B1;
        for (int k0 = 0; k0 < K; k0 += 16) {
            #pragma unroll
            for (int t = 0; t < 2; ++t) {
                int i = tid + t * 256;
                As[i & 15][i >> 4] = A[(m0 + (i >> 4)) * K + k0 + (i & 15)];
            }
            #pragma unroll
            for (int t = 0; t < 4; ++t) {
                int i = tid + t * 256;
                Bs[i >> 6][i & 63] = B[(k0 + (i >> 6)) * N + n0 + (i & 63)];
            }
            __syncthreads();
            #pragma unroll
            for (int kk = 0; kk < 16; ++kk) {
                float2 av = *(const float2*)&As[kk][ty * 2];
                ulonglong2 bv = *(const ulonglong2*)&Bs[kk][tx * 4];
                ull a0 = pk2(av.x, av.x);
                ull a1 = pk2(av.y, av.y);
                acc[0][0] = fma2(a0, bv.x, acc[0][0]);
                acc[0][1] = fma2(a0, bv.y, acc[0][1]);
                acc[1][0] = fma2(a1, bv.x, acc[1][0]);
                acc[1][1] = fma2(a1, bv.y, acc[1][1]);
            }
            __syncthreads();
        }
    }

    int n = n0 + tx * 4;
    float b0 = 0.f, b1 = 0.f, b2 = 0.f, b3 = 0.f;
    if (add_bias) { b0 = bias[n]; b1 = bias[n+1]; b2 = bias[n+2]; b3 = bias[n+3]; }
    #pragma unroll
    for (int r = 0; r < 2; ++r) {
        int m = m0 + ty * 2 + r;
        float2 lo = upk(acc[r][0]);
        float2 hi = upk(acc[r][1]);
        float4 o = make_float4(lo.x + b0, lo.y + b1, hi.x + b2, hi.y + b3);
        *(float4*)&C[m * N + n] = o;
    }
}

__global__ void __launch_bounds__(256) phase1_kernel(
    const float* __restrict__ x,     const float* __restrict__ kernel,
    const float* __restrict__ h_tm1, const float* __restrict__ rec,
    const float* __restrict__ bias,  const float* __restrict__ w,
    const float* __restrict__ hebb,
    float* __restrict__ pre, float* __restrict__ hw, float* __restrict__ part)
{
    int bid = blockIdx.x;
    int tid = threadIdx.x;

    if (bid < 320) {
        __shared__ __align__(16) float smem[1536];
        if (bid < 256) {
            int n0 = (bid & 31) * 64;
            int m0 = (bid >> 5) * 32;
            bool do_rec = !(n0 >= 2 * Udim && n0 < 3 * Udim);  // c-slice: no rec
            gemm32x64(x, kernel, h_tm1, rec, bias, pre, N4U, m0, n0, do_rec, true, smem);
        } else {
            int t  = bid - 256;
            int n0 = (t & 7) * 64;
            int m0 = (t >> 3) * 32;
            gemm32x64(h_tm1, w, nullptr, nullptr, nullptr, hw, Udim, m0, n0, false, false, smem);
        }
    } else {
        // ---- pure per-thread hebb partial reduce ----
        // g over (b, u0, v4): v4 = g&127, u0 = (g>>7)&127, b = g>>14
        // folds u = u0 + {0,128,256,384}. No smem. No sync.
        int g   = (bid - 320) * 256 + tid;
        int v4  = g & 127;
        int u0  = (g >> 7) & 127;
        int b   = g >> 14;

        int X = (b << 16) | (u0 << 7) | v4;   // f4 index into hebb  (65536 f4 / b)
        int Y = (b << 14) | (u0 << 7) | v4;   // f4 index into part  (16384 f4 / b)

        float hu0 = h_tm1[(b << 9) + u0];
        float hu1 = h_tm1[(b << 9) + u0 + 128];
        float hu2 = h_tm1[(b << 9) + u0 + 256];
        float hu3 = h_tm1[(b << 9) + u0 + 384];

        float4 l0 = __ldcs(((const float4*)hebb) + X);
        float4 l1 = __ldcs(((const float4*)hebb) + X + 16384);
        float4 l2 = __ldcs(((const float4*)hebb) + X + 32768);
        float4 l3 = __ldcs(((const float4*)hebb) + X + 49152);

        ull h0 = pk2(hu0, hu0), h1 = pk2(hu1, hu1);
        ull h2 = pk2(hu2, hu2), h3 = pk2(hu3, hu3);
        ulonglong2 v0 = *(ulonglong2*)&l0;
        ulonglong2 v1 = *(ulonglong2*)&l1;
        ulonglong2 v2 = *(ulonglong2*)&l2;
        ulonglong2 v3 = *(ulonglong2*)&l3;

        ull ax = fma2(h1, v1.x, fma2(h0, v0.x, 0ull));
        ull bx = fma2(h3, v3.x, fma2(h2, v2.x, 0ull));
        ull ay = fma2(h1, v1.y, fma2(h0, v0.y, 0ull));
        ull by = fma2(h3, v3.y, fma2(h2, v2.y, 0ull));

        float2 px = upk(ax), qx = upk(bx);
        float2 py = upk(ay), qy = upk(by);
        float4 acc = make_float4(px.x + qx.x, px.y + qx.y, py.x + qy.x, py.y + qy.y);

        __stcs(((float4*)part) + Y, acc);
    }
}

// =======================================================================
// Phase 2: combine — fold 128 partials, gates, c, h, eta, g (256 x 512)
// =======================================================================
__device__ __forceinline__ float hsig(float z) {
    return fminf(fmaxf(0.2f * z + 0.5f, 0.f), 1.f);
}

__global__ void __launch_bounds__(512) combine_kernel(
    const float* __restrict__ pre, const float* __restrict__ hw,
    const float* __restrict__ part, const float* __restrict__ c_tm1,
    const float* __restrict__ alpha, const float* __restrict__ h2mod,
    const float* __restrict__ fanout,
    float* __restrict__ out, float* __restrict__ g)
{
    int b = blockIdx.x;
    int v = threadIdx.x;

    // fold 128 partials: part_f[b*65536 + u0*512 + v], coalesced across v
    const float* r = part + ((size_t)b << 16) + v;
    float p0 = 0.f, p1 = 0.f, p2 = 0.f, p3 = 0.f;
    #pragma unroll 8
    for (int j = 0; j < 128; j += 4) {
        p0 += r[(j + 0) << 9];
        p1 += r[(j + 1) << 9];
        p2 += r[(j + 2) << 9];
        p3 += r[(j + 3) << 9];
    }
    float red = (p0 + p1) + (p2 + p3);

    float xi = pre[b * N4U + v];
    float xf = pre[b * N4U + Udim + v];
    float xc = pre[b * N4U + 2 * Udim + v];
    float xo = pre[b * N4U + 3 * Udim + v];

    float gi = hsig(xi), gf = hsig(xf), go = hsig(xo);
    float itc = tanhf(xc + hw[b * Udim + v] + alpha[v] * red);
    float c = gf * c_tm1[b * Udim + v] + gi * itc;
    float h = go * tanhf(c);

    out[b * Udim + v] = h;
    out[Bdim * Udim + b * Udim + v] = c;

    float s = h * h2mod[v];
    #pragma unroll
    for (int o = 16; o > 0; o >>= 1) s += __shfl_down_sync(0xffffffffu, s, o);
    __shared__ float ws[16];
    __shared__ float eta_s;
    if ((v & 31) == 0) ws[v >> 5] = s;
    __syncthreads();
    if (v < 16) {
        float tt = ws[v];
        #pragma unroll
        for (int o = 8; o > 0; o >>= 1) tt += __shfl_down_sync(0xffffu, tt, o);
        if (v == 0) eta_s = tanhf(tt);
    }
    __syncthreads();
    g[b * Udim + v] = eta_s * fanout[v] * itc;
}

// =======================================================================
// Phase 3: hebb update — unchanged
// =======================================================================
__global__ void __launch_bounds__(256) hebb_update(
    const float* __restrict__ hebb, const float* __restrict__ h_tm1,
    const float* __restrict__ g, float* __restrict__ out)
{
    int base = blockIdx.x * 1024 + threadIdx.x;

    #pragma unroll
    for (int k = 0; k < 4; ++k) {
        int idx = base + k * 256;
        int row = idx >> 7;
        int v4  = idx & 127;
        int b   = idx >> 16;

        float hu = h_tm1[row];
        float4 hv = __ldcs(((const float4*)hebb) + idx);
        float4 gg = ((const float4*)(g + b * Udim))[v4];

        float4 r;
        r.x = fminf(fmaxf(hv.x + hu * gg.x, -2.f), 2.f);
        r.y = fminf(fmaxf(hv.y + hu * gg.y, -2.f), 2.f);
        r.z = fminf(fmaxf(hv.z + hu * gg.z, -2.f), 2.f);
        r.w = fminf(fmaxf(hv.w + hu * gg.w, -2.f), 2.f);
        __stcs(((float4*)out) + idx, r);
    }
}

// ---------------- launch (single stream) ----------------
extern "C" void kernel_launch(void* const* d_in, const int* in_sizes, int n_in,
                              void* d_out, int out_size)
{
    const float* x      = (const float*)d_in[0];
    const float* h_tm1  = (const float*)d_in[1];
    const float* c_tm1  = (const float*)d_in[2];
    const float* hebb   = (const float*)d_in[3];
    const float* kernel = (const float*)d_in[4];
    const float* rec    = (const float*)d_in[5];
    const float* bias   = (const float*)d_in[6];
    const float* w      = (const float*)d_in[7];
    const float* alpha  = (const float*)d_in[8];
    const float* h2mod  = (const float*)d_in[9];
    const float* fanout = (const float*)d_in[10];
    float* out = (float*)d_out;

    float *pre, *hw, *part, *gg;
    cudaGetSymbolAddress((void**)&pre,  g_pre);
    cudaGetSymbolAddress((void**)&hw,   g_hw);
    cudaGetSymbolAddress((void**)&part, g_part);
    cudaGetSymbolAddress((void**)&gg,   g_g);

    phase1_kernel<<<320 + 16384, 256>>>(x, kernel, h_tm1, rec, bias, w, hebb,
                                        pre, hw, part);
    combine_kernel<<<Bdim, Udim>>>(pre, hw, part, c_tm1, alpha, h2mod, fanout, out, gg);
    hebb_update<<<16384, 256>>>(hebb, h_tm1, gg, out + 2 * Bdim * Udim);
}

// round 11
// speedup vs baseline: 1.0447x; 1.0447x over previous
#include <cuda_runtime.h>
#include <cstdint>

#define Bdim 256
#define Udim 512
#define Ddim 512
#define N4U  2048

typedef unsigned long long ull;

// ---------------- scratch ----------------
__device__ float g_pre  [Bdim * N4U];
__device__ float g_hw   [Bdim * Udim];
__device__ float g_red16[Bdim * 16 * Udim];   // 16 partials per (b,v)
__device__ float g_g    [Bdim * Udim];

// ---------------- packed f32x2 helpers ----------------
__device__ __forceinline__ ull pk2(float x, float y) {
    ull r; asm("mov.b64 %0, {%1, %2};" : "=l"(r) : "f"(x), "f"(y)); return r;
}
__device__ __forceinline__ ull fma2(ull a, ull b, ull c) {
    ull d; asm("fma.rn.f32x2 %0, %1, %2, %3;" : "=l"(d) : "l"(a), "l"(b), "l"(c)); return d;
}
__device__ __forceinline__ float2 upk(ull v) {
    float2 r; asm("mov.b64 {%0, %1}, %2;" : "=f"(r.x), "=f"(r.y) : "l"(v)); return r;
}

// ---------------- TMA / mbarrier helpers ----------------
__device__ __forceinline__ uint32_t smem_u32(const void* p) {
    uint32_t a;
    asm("{ .reg .u64 t; cvta.to.shared.u64 t, %1; cvt.u32.u64 %0, t; }"
        : "=r"(a) : "l"(p));
    return a;
}
__device__ __forceinline__ void mbar_init(uint32_t mbar, uint32_t cnt) {
    asm volatile("mbarrier.init.shared.b64 [%0], %1;" :: "r"(mbar), "r"(cnt) : "memory");
}
__device__ __forceinline__ void mbar_expect_tx(uint32_t mbar, uint32_t bytes) {
    asm volatile("mbarrier.arrive.expect_tx.shared.b64 _, [%0], %1;"
                 :: "r"(mbar), "r"(bytes) : "memory");
}
__device__ __forceinline__ void bulk_g2s(uint32_t dst, const void* src,
                                         uint32_t bytes, uint32_t mbar) {
    asm volatile(
        "cp.async.bulk.shared::cta.global.mbarrier::complete_tx::bytes [%0], [%1], %2, [%3];"
        :: "r"(dst), "l"(src), "r"(bytes), "r"(mbar) : "memory");
}
__device__ __forceinline__ void mbar_wait(uint32_t mbar, uint32_t parity) {
    asm volatile(
        "{\n\t"
        ".reg .pred P;\n\t"
        "WAIT_%=:\n\t"
        "mbarrier.try_wait.parity.acquire.cta.shared::cta.b64 P, [%0], %1, 0x989680;\n\t"
        "@P bra DONE_%=;\n\t"
        "bra WAIT_%=;\n\t"
        "DONE_%=:\n\t"
        "}"
        :: "r"(mbar), "r"(parity) : "memory");
}

// =======================================================================
// Phase 1: one kernel
//   [0, 256)        : gates GEMM, 32x64 tiles
//   [256, 320)      : hw GEMM,    32x64 tiles
//   [320, 320+4096) : hebb partial reduce via TMA double-buffer pipeline
// =======================================================================

__device__ __forceinline__ void gemm32x64(
    const float* __restrict__ A1, const float* __restrict__ B1,
    const float* __restrict__ A2, const float* __restrict__ B2,
    const float* __restrict__ bias, float* __restrict__ C,
    int N, int m0, int n0, bool do_rec, bool add_bias, float* smem)
{
    const int K = 512;
    float (*As)[32] = (float(*)[32])smem;
    float (*Bs)[64] = (float(*)[64])(smem + 512);

    int tid = threadIdx.x;
    int tx  = tid & 15;
    int ty  = tid >> 4;

    ull acc[2][2];
    acc[0][0] = acc[0][1] = acc[1][0] = acc[1][1] = 0ull;

    int npass = do_rec ? 2 : 1;
    for (int pass = 0; pass < npass; ++pass) {
        const float* A = pass ? A2 : A1;
        const float* B = pass ? B2 : B1;
        for (int k0 = 0; k0 < K; k0 += 16) {
            #pragma unroll
            for (int t = 0; t < 2; ++t) {
                int i = tid + t * 256;
                As[i & 15][i >> 4] = A[(m0 + (i >> 4)) * K + k0 + (i & 15)];
            }
            #pragma unroll
            for (int t = 0; t < 4; ++t) {
                int i = tid + t * 256;
                Bs[i >> 6][i & 63] = B[(k0 + (i >> 6)) * N + n0 + (i & 63)];
            }
            __syncthreads();
            #pragma unroll
            for (int kk = 0; kk < 16; ++kk) {
                float2 av = *(const float2*)&As[kk][ty * 2];
                ulonglong2 bv = *(const ulonglong2*)&Bs[kk][tx * 4];
                ull a0 = pk2(av.x, av.x);
                ull a1 = pk2(av.y, av.y);
                acc[0][0] = fma2(a0, bv.x, acc[0][0]);
                acc[0][1] = fma2(a0, bv.y, acc[0][1]);
                acc[1][0] = fma2(a1, bv.x, acc[1][0]);
                acc[1][1] = fma2(a1, bv.y, acc[1][1]);
            }
            __syncthreads();
        }
    }

    int n = n0 + tx * 4;
    float b0 = 0.f, b1 = 0.f, b2 = 0.f, b3 = 0.f;
    if (add_bias) { b0 = bias[n]; b1 = bias[n+1]; b2 = bias[n+2]; b3 = bias[n+3]; }
    #pragma unroll
    for (int r = 0; r < 2; ++r) {
        int m = m0 + ty * 2 + r;
        float2 lo = upk(acc[r][0]);
        float2 hi = upk(acc[r][1]);
        float4 o = make_float4(lo.x + b0, lo.y + b1, hi.x + b2, hi.y + b3);
        *(float4*)&C[m * N + n] = o;
    }
}

__global__ void __launch_bounds__(256) phase1_kernel(
    const float* __restrict__ x,     const float* __restrict__ kernel,
    const float* __restrict__ h_tm1, const float* __restrict__ rec,
    const float* __restrict__ bias,  const float* __restrict__ w,
    const float* __restrict__ hebb,
    float* __restrict__ pre, float* __restrict__ hw, float* __restrict__ red16)
{
    // layout: [0,8192) two 16KB buffers | [8192,8256) hs2 (ull[32]) | [8256,8260) mbars
    __shared__ __align__(16) float smem[8272];
    int bid = blockIdx.x;
    int tid = threadIdx.x;

    if (bid < 320) {
        if (bid < 256) {
            int n0 = (bid & 31) * 64;
            int m0 = (bid >> 5) * 32;
            bool do_rec = !(n0 >= 2 * Udim && n0 < 3 * Udim);  // c-slice: no rec
            gemm32x64(x, kernel, h_tm1, rec, bias, pre, N4U, m0, n0, do_rec, true, smem);
        } else {
            int t  = bid - 256;
            int n0 = (t & 7) * 64;
            int m0 = (t >> 3) * 32;
            gemm32x64(h_tm1, w, nullptr, nullptr, nullptr, hw, Udim, m0, n0, false, false, smem);
        }
        return;
    }

    // ---- TMA-fed hebb partial reduce ----
    // block: (b, 32-u chunk). 4 iterations x 8 u-rows (16KB tiles), 2 buffers.
    int t     = bid - 320;        // 0..4095
    int b     = t >> 4;
    int chunk = t & 15;
    int v4    = tid & 127;        // f4 column
    int uh    = tid >> 7;         // half: rows 0-3 or 4-7 of each tile

    const float* src = hebb + ((size_t)b << 18) + ((size_t)chunk << 14); // 32 rows x 512

    uint32_t sbase = smem_u32(smem);
    uint32_t mbar0 = sbase + 8256 * 4;
    uint32_t mbar1 = mbar0 + 8;

    ull* hs2 = (ull*)(smem + 8192);
    if (tid < 32) {
        float hv = h_tm1[(b << 9) + (chunk << 5) + tid];
        hs2[tid] = pk2(hv, hv);
    }
    if (tid == 0) {
        mbar_init(mbar0, 1);
        mbar_init(mbar1, 1);
    }
    __syncthreads();

    if (tid == 0) {
        mbar_expect_tx(mbar0, 16384);
        bulk_g2s(sbase, src, 16384, mbar0);
        mbar_expect_tx(mbar1, 16384);
        bulk_g2s(sbase + 16384, src + 4096, 16384, mbar1);
    }

    ull ax = 0ull, ay = 0ull;
    #pragma unroll
    for (int i = 0; i < 4; ++i) {
        int s = i & 1;
        uint32_t mb = s ? mbar1 : mbar0;
        mbar_wait(mb, (i >> 1) & 1);

        const float4* bp = (const float4*)(smem + s * 4096) + (uh * 4) * 128 + v4;
        const ull* hb = hs2 + i * 8 + uh * 4;
        #pragma unroll
        for (int j = 0; j < 4; ++j) {
            float4 l = bp[j * 128];
            ulonglong2 lv = *(ulonglong2*)&l;
            ull hd = hb[j];
            ax = fma2(hd, lv.x, ax);
            ay = fma2(hd, lv.y, ay);
        }
        __syncthreads();
        if (i < 2 && tid == 0) {
            mbar_expect_tx(mb, 16384);
            bulk_g2s(sbase + s * 16384, src + (i + 2) * 4096, 16384, mb);
        }
    }

    float2 fx = upk(ax), fy = upk(ay);
    float4 acc = make_float4(fx.x, fx.y, fy.x, fy.y);

    // fold halves via buf0 (free after iter 2) — ordered by loop's last syncthreads
    float4* st = (float4*)smem;
    if (uh == 1) st[v4] = acc;
    __syncthreads();
    if (uh == 0) {
        float4 o = st[v4];
        acc.x += o.x; acc.y += o.y; acc.z += o.z; acc.w += o.w;
        ((float4*)(red16 + (size_t)(b * 16 + chunk) * Udim))[v4] = acc;
    }
}

// =======================================================================
// Phase 2: combine — gates, c, h, eta reduction, g   (256 blocks x 512)
// =======================================================================
__device__ __forceinline__ float hsig(float z) {
    return fminf(fmaxf(0.2f * z + 0.5f, 0.f), 1.f);
}

__global__ void __launch_bounds__(512) combine_kernel(
    const float* __restrict__ pre, const float* __restrict__ hw,
    const float* __restrict__ red16, const float* __restrict__ c_tm1,
    const float* __restrict__ alpha, const float* __restrict__ h2mod,
    const float* __restrict__ fanout,
    float* __restrict__ out, float* __restrict__ g)
{
    int b = blockIdx.x;
    int v = threadIdx.x;

    const float* r = red16 + (size_t)b * 16 * Udim;
    float p0 = 0.f, p1 = 0.f, p2 = 0.f, p3 = 0.f;
    #pragma unroll
    for (int j = 0; j < 16; j += 4) {
        p0 += r[(j + 0) * Udim + v];
        p1 += r[(j + 1) * Udim + v];
        p2 += r[(j + 2) * Udim + v];
        p3 += r[(j + 3) * Udim + v];
    }
    float red = (p0 + p1) + (p2 + p3);

    float xi = pre[b * N4U + v];
    float xf = pre[b * N4U + Udim + v];
    float xc = pre[b * N4U + 2 * Udim + v];
    float xo = pre[b * N4U + 3 * Udim + v];

    float gi = hsig(xi), gf = hsig(xf), go = hsig(xo);
    float itc = tanhf(xc + hw[b * Udim + v] + alpha[v] * red);
    float c = gf * c_tm1[b * Udim + v] + gi * itc;
    float h = go * tanhf(c);

    out[b * Udim + v] = h;
    out[Bdim * Udim + b * Udim + v] = c;

    float s = h * h2mod[v];
    #pragma unroll
    for (int o = 16; o > 0; o >>= 1) s += __shfl_down_sync(0xffffffffu, s, o);
    __shared__ float ws[16];
    __shared__ float eta_s;
    if ((v & 31) == 0) ws[v >> 5] = s;
    __syncthreads();
    if (v < 16) {
        float tt = ws[v];
        #pragma unroll
        for (int o = 8; o > 0; o >>= 1) tt += __shfl_down_sync(0xffffu, tt, o);
        if (v == 0) eta_s = tanhf(tt);
    }
    __syncthreads();
    g[b * Udim + v] = eta_s * fanout[v] * itc;
}

// =======================================================================
// Phase 3: hebb update — unchanged (near roofline)
// =======================================================================
__global__ void __launch_bounds__(256) hebb_update(
    const float* __restrict__ hebb, const float* __restrict__ h_tm1,
    const float* __restrict__ g, float* __restrict__ out)
{
    int base = blockIdx.x * 1024 + threadIdx.x;

    #pragma unroll
    for (int k = 0; k < 4; ++k) {
        int idx = base + k * 256;
        int row = idx >> 7;
        int v4  = idx & 127;
        int b   = idx >> 16;

        float hu = h_tm1[row];
        float4 hv = __ldcs(((const float4*)hebb) + idx);
        float4 gg = ((const float4*)(g + b * Udim))[v4];

        float4 r;
        r.x = fminf(fmaxf(hv.x + hu * gg.x, -2.f), 2.f);
        r.y = fminf(fmaxf(hv.y + hu * gg.y, -2.f), 2.f);
        r.z = fminf(fmaxf(hv.z + hu * gg.z, -2.f), 2.f);
        r.w = fminf(fmaxf(hv.w + hu * gg.w, -2.f), 2.f);
        __stcs(((float4*)out) + idx, r);
    }
}

// ---------------- launch (single stream) ----------------
extern "C" void kernel_launch(void* const* d_in, const int* in_sizes, int n_in,
                              void* d_out, int out_size)
{
    const float* x      = (const float*)d_in[0];
    const float* h_tm1  = (const float*)d_in[1];
    const float* c_tm1  = (const float*)d_in[2];
    const float* hebb   = (const float*)d_in[3];
    const float* kernel = (const float*)d_in[4];
    const float* rec    = (const float*)d_in[5];
    const float* bias   = (const float*)d_in[6];
    const float* w      = (const float*)d_in[7];
    const float* alpha  = (const float*)d_in[8];
    const float* h2mod  = (const float*)d_in[9];
    const float* fanout = (const float*)d_in[10];
    float* out = (float*)d_out;

    float *pre, *hw, *red16, *gg;
    cudaGetSymbolAddress((void**)&pre,   g_pre);
    cudaGetSymbolAddress((void**)&hw,    g_hw);
    cudaGetSymbolAddress((void**)&red16, g_red16);
    cudaGetSymbolAddress((void**)&gg,    g_g);

    phase1_kernel<<<320 + 4096, 256>>>(x, kernel, h_tm1, rec, bias, w, hebb,
                                       pre, hw, red16);
    combine_kernel<<<Bdim, Udim>>>(pre, hw, red16, c_tm1, alpha, h2mod, fanout, out, gg);
    hebb_update<<<16384, 256>>>(hebb, h_tm1, gg, out + 2 * Bdim * Udim);
}